// round 2
// baseline (speedup 1.0000x reference)
#include <cuda_runtime.h>

#define N_ELEMS 8192
#define NT 256
#define JT 512
#define NI_BLOCKS (N_ELEMS / NT)          // 32
#define NJ_BLOCKS (N_ELEMS / JT)          // 16
#define NPAIR_BLOCKS (NI_BLOCKS * NJ_BLOCKS)  // 512

// Scratch (no cudaMalloc allowed)
__device__ float     g_d[N_ELEMS];
__device__ float     g_bce[NI_BLOCKS];
__device__ float     g_sq[NPAIR_BLOCKS];
__device__ int       g_cnt[NPAIR_BLOCKS];

__device__ __forceinline__ float warp_sum_f(float v) {
#pragma unroll
    for (int o = 16; o > 0; o >>= 1) v += __shfl_down_sync(0xffffffffu, v, o);
    return v;
}
__device__ __forceinline__ int warp_sum_i(int v) {
#pragma unroll
    for (int o = 16; o > 0; o >>= 1) v += __shfl_down_sync(0xffffffffu, v, o);
    return v;
}

// Kernel 1: per-element BCE term + d_i = pred_i - logit(clamp(psi_i))
__global__ void prep_kernel(const float* __restrict__ pred,
                            const float* __restrict__ psi) {
    int i = blockIdx.x * NT + threadIdx.x;
    float x = pred[i];
    float t = psi[i];

    // numerically stable BCE-with-logits term
    float term = fmaxf(x, 0.0f) - x * t + log1pf(expf(-fabsf(x)));

    // logit with clamp [eps, 1-eps]
    const float EPS = 1e-7f;
    const float HI  = 1.0f - 1e-7f;   // folds to 0.99999988f, matches jnp fp32
    float p = fminf(fmaxf(t, EPS), HI);
    float lg = logf(p) - log1pf(-p);
    g_d[i] = x - lg;

    // block-reduce BCE partial
    __shared__ float sw[NT / 32];
    float s = warp_sum_f(term);
    if ((threadIdx.x & 31) == 0) sw[threadIdx.x >> 5] = s;
    __syncthreads();
    if (threadIdx.x < 32) {
        float v = (threadIdx.x < NT / 32) ? sw[threadIdx.x] : 0.0f;
        v = warp_sum_f(v);
        if (threadIdx.x == 0) g_bce[blockIdx.x] = v;
    }
}

// Kernel 2: all-pairs masked sum of (d_i - d_j)^2 and valid count.
// blockIdx.x -> chunk of 256 i's (one per lane), blockIdx.y -> chunk of 512 j's.
// All lanes in a warp sweep the same j => shared-mem broadcast loads.
__global__ void pair_kernel(const float* __restrict__ psi) {
    __shared__ float s_d[JT];
    __shared__ float s_p[JT];

    int i  = blockIdx.x * NT + threadIdx.x;
    int j0 = blockIdx.y * JT;

    for (int k = threadIdx.x; k < JT; k += NT) {
        s_d[k] = g_d[j0 + k];
        s_p[k] = psi[j0 + k];
    }
    __syncthreads();

    float di = g_d[i];
    float pi = psi[i];

    float sq  = 0.0f;
    int   cnt = 0;
#pragma unroll 16
    for (int k = 0; k < JT; k++) {
        float ori = pi - s_p[k];
        float dd  = di - s_d[k];
        if (fabsf(ori) >= 0.05f) {
            sq = fmaf(dd, dd, sq);
            cnt++;
        }
    }

    // block reduce
    __shared__ float swf[NT / 32];
    __shared__ int   swi[NT / 32];
    float s = warp_sum_f(sq);
    int   c = warp_sum_i(cnt);
    if ((threadIdx.x & 31) == 0) {
        swf[threadIdx.x >> 5] = s;
        swi[threadIdx.x >> 5] = c;
    }
    __syncthreads();
    if (threadIdx.x < 32) {
        float v  = (threadIdx.x < NT / 32) ? swf[threadIdx.x] : 0.0f;
        int   ci = (threadIdx.x < NT / 32) ? swi[threadIdx.x] : 0;
        v  = warp_sum_f(v);
        ci = warp_sum_i(ci);
        if (threadIdx.x == 0) {
            int b = blockIdx.y * gridDim.x + blockIdx.x;
            g_sq[b]  = v;
            g_cnt[b] = ci;
        }
    }
}

// Kernel 3: final reduction + scalar assembly. One block, NPAIR_BLOCKS threads.
__global__ void final_kernel(const int* __restrict__ flag,
                             float* __restrict__ out) {
    int t = threadIdx.x;
    double    sq  = (double)g_sq[t];
    long long cnt = (long long)g_cnt[t];
    float     bce = (t < NI_BLOCKS) ? g_bce[t] : 0.0f;

#pragma unroll
    for (int o = 16; o > 0; o >>= 1) {
        sq  += __shfl_down_sync(0xffffffffu, sq, o);
        cnt += __shfl_down_sync(0xffffffffu, cnt, o);
        bce += __shfl_down_sync(0xffffffffu, bce, o);
    }

    __shared__ double    ssq[NPAIR_BLOCKS / 32];
    __shared__ long long scnt[NPAIR_BLOCKS / 32];
    __shared__ float     sb[NPAIR_BLOCKS / 32];
    if ((t & 31) == 0) {
        ssq[t >> 5]  = sq;
        scnt[t >> 5] = cnt;
        sb[t >> 5]   = bce;
    }
    __syncthreads();
    if (t < 32) {
        const int NW = NPAIR_BLOCKS / 32;  // 16
        double    q = (t < NW) ? ssq[t] : 0.0;
        long long c = (t < NW) ? scnt[t] : 0;
        float     b = (t < NW) ? sb[t] : 0.0f;
#pragma unroll
        for (int o = 16; o > 0; o >>= 1) {
            q += __shfl_down_sync(0xffffffffu, q, o);
            c += __shfl_down_sync(0xffffffffu, c, o);
            b += __shfl_down_sync(0xffffffffu, b, o);
        }
        if (t == 0) {
            float loss = b / (float)N_ELEMS;
            float res  = loss;
            if (*flag == 0 && c > 0) {
                float mse = (float)(q / (double)c);
                res = loss + 10.0f * mse;
            }
            out[0] = res;
        }
    }
}

extern "C" void kernel_launch(void* const* d_in, const int* in_sizes, int n_in,
                              void* d_out, int out_size) {
    const float* pred = (const float*)d_in[0];
    const float* psi  = (const float*)d_in[1];
    const int*   flag = (const int*)d_in[2];
    float* out = (float*)d_out;

    prep_kernel<<<NI_BLOCKS, NT>>>(pred, psi);
    dim3 grid(NI_BLOCKS, NJ_BLOCKS);
    pair_kernel<<<grid, NT>>>(psi);
    final_kernel<<<1, NPAIR_BLOCKS>>>(flag, out);
}

// round 3
// speedup vs baseline: 1.1928x; 1.1928x over previous
#include <cuda_runtime.h>

#define N_ELEMS 8192
#define NT 256
#define NBLK 32                     // prep / scatter blocks (32 x 256 = 8192)
#define NBUCK 20                    // psi buckets of width 0.05
#define TH 0.05f
#define PAIR_BLOCKS 128             // 128 x 64 i's = 8192
#define I_PER_BLOCK 64
#define JSPLIT 4
#define WCAP 4096                   // smem j-window capacity (floats)

// ---- scratch (__device__ globals; no allocation allowed) ----
__device__ float g_d[N_ELEMS];          // pred - logit(psi), original order
__device__ float g_spsi[N_ELEMS];       // psi, bucket-sorted
__device__ float g_sdd[N_ELEMS];        // d,   bucket-sorted
__device__ int   g_hist[NBLK * NBUCK];  // per-prep-block bucket histograms
__device__ int   g_off[NBUCK + 1];      // bucket offsets in sorted layout
__device__ float g_bce[NBLK];
__device__ float g_sd[NBLK];
__device__ float g_sd2[NBLK];
__device__ float g_psq[PAIR_BLOCKS];    // invalid-pair sq partials
__device__ int   g_pcnt[PAIR_BLOCKS];   // invalid-pair count partials

__device__ __forceinline__ float warp_sum_f(float v) {
#pragma unroll
    for (int o = 16; o > 0; o >>= 1) v += __shfl_down_sync(0xffffffffu, v, o);
    return v;
}

__device__ __forceinline__ int bucket_of(float p) {
    int b = (int)(p * 20.0f);
    return b > (NBUCK - 1) ? (NBUCK - 1) : b;
}

// ---------------------------------------------------------------------------
// Kernel 1: per-element BCE term, d_i, bucket histogram, and O(N) sums
// ---------------------------------------------------------------------------
__global__ void prep_kernel(const float* __restrict__ pred,
                            const float* __restrict__ psi) {
    __shared__ int   hist[NBUCK];
    __shared__ float sw1[NT / 32], sw2[NT / 32], sw3[NT / 32];
    int tid = threadIdx.x;
    if (tid < NBUCK) hist[tid] = 0;
    __syncthreads();

    int i = blockIdx.x * NT + tid;
    float x = pred[i];
    float t = psi[i];

    // stable BCE-with-logits term (fast math; rel err ~2^-22, negligible)
    float term = fmaxf(x, 0.0f) - x * t + __logf(1.0f + __expf(-fabsf(x)));

    // logit with clamp [eps, 1-eps]
    float p = fminf(fmaxf(t, 1e-7f), 1.0f - 1e-7f);
    float lg = __logf(p) - __logf(1.0f - p);
    float d = x - lg;
    g_d[i] = d;

    atomicAdd(&hist[bucket_of(t)], 1);

    float s1 = warp_sum_f(term);
    float s2 = warp_sum_f(d);
    float s3 = warp_sum_f(d * d);
    if ((tid & 31) == 0) {
        sw1[tid >> 5] = s1; sw2[tid >> 5] = s2; sw3[tid >> 5] = s3;
    }
    __syncthreads();
    if (tid < 32) {
        float v1 = (tid < NT / 32) ? sw1[tid] : 0.0f;
        float v2 = (tid < NT / 32) ? sw2[tid] : 0.0f;
        float v3 = (tid < NT / 32) ? sw3[tid] : 0.0f;
        v1 = warp_sum_f(v1); v2 = warp_sum_f(v2); v3 = warp_sum_f(v3);
        if (tid == 0) {
            g_bce[blockIdx.x] = v1;
            g_sd[blockIdx.x]  = v2;
            g_sd2[blockIdx.x] = v3;
        }
    }
    if (tid < NBUCK) g_hist[blockIdx.x * NBUCK + tid] = hist[tid];
}

// ---------------------------------------------------------------------------
// Kernel 2: deterministic counting-sort scatter of (psi, d) into bucket order
// ---------------------------------------------------------------------------
__global__ void scatter_kernel(const float* __restrict__ psi) {
    __shared__ int part[NBLK * NBUCK];
    __shared__ int tot[NBUCK];
    __shared__ int base[NBUCK + 1];
    __shared__ int blkoff[NBUCK];
    __shared__ int wcnt[NT / 32][NBUCK];

    int tid = threadIdx.x, blk = blockIdx.x;
    for (int k = tid; k < NBLK * NBUCK; k += NT) part[k] = g_hist[k];
    if (tid < (NT / 32) * NBUCK) ((int*)wcnt)[tid] = 0;
    __syncthreads();

    if (tid < NBUCK) {
        int s = 0, so = 0;
        for (int k = 0; k < NBLK; k++) {
            int v = part[k * NBUCK + tid];
            s += v;
            if (k < blk) so += v;
        }
        tot[tid] = s;
        blkoff[tid] = so;
    }
    __syncthreads();
    if (tid == 0) {
        int run = 0;
        for (int b = 0; b < NBUCK; b++) { base[b] = run; run += tot[b]; }
        base[NBUCK] = run;  // == N
    }
    __syncthreads();
    if (blk == 0 && tid <= NBUCK) g_off[tid] = base[tid];

    int i = blk * NT + tid;
    float t = psi[i];
    float d = g_d[i];
    int b = bucket_of(t);

    // deterministic rank within block: warp match + per-warp counts
    unsigned m = __match_any_sync(0xffffffffu, b);
    int lane = tid & 31, w = tid >> 5;
    int lr = __popc(m & ((1u << lane) - 1u));
    if (lr == 0) wcnt[w][b] = __popc(m);
    __syncthreads();
    int r = lr;
    for (int ww = 0; ww < w; ww++) r += wcnt[ww][b];

    int pos = base[b] + blkoff[b] + r;
    g_spsi[pos] = t;
    g_sdd[pos]  = d;
}

// ---------------------------------------------------------------------------
// Kernel 3: INVALID pairs only (|dpsi| < th) — bucket distance <= 1.
// Each block: 64 consecutive sorted i's x 4 j-splits. Contiguous j-window
// [off[b-1], off[b+2]) cached in smem.
// ---------------------------------------------------------------------------
__global__ void pair_kernel() {
    __shared__ float SP[WCAP];
    __shared__ float SD[WCAP];
    __shared__ int   off[NBUCK + 1];
    __shared__ float swf[NT / 32];
    __shared__ int   swi[NT / 32];

    int tid = threadIdx.x;
    if (tid <= NBUCK) off[tid] = g_off[tid];
    __syncthreads();

    int i_base = blockIdx.x * I_PER_BLOCK;
    float p_first = g_spsi[i_base];
    float p_last  = g_spsi[i_base + I_PER_BLOCK - 1];
    int b0 = bucket_of(p_first);
    int b1 = bucket_of(p_last);
    int lo_b = max(b0 - 1, 0), hi_b = min(b1 + 2, NBUCK);
    int wlo = off[lo_b], whi = off[hi_b];
    int wn = whi - wlo;
    bool use_s = (wn <= WCAP);
    if (use_s) {
        for (int k = tid; k < wn; k += NT) {
            SP[k] = g_spsi[wlo + k];
            SD[k] = g_sdd[wlo + k];
        }
    }
    __syncthreads();

    int il = tid & (I_PER_BLOCK - 1);
    int js = tid / I_PER_BLOCK;
    int i = i_base + il;
    float pi = g_spsi[i];
    float di = g_sdd[i];
    int bi = bucket_of(pi);
    int lo = off[max(bi - 1, 0)] - wlo;
    int hi = off[min(bi + 2, NBUCK)] - wlo;

    float sq = 0.0f;
    int cnt = 0;
    if (use_s) {
#pragma unroll 4
        for (int k = lo + js; k < hi; k += JSPLIT) {
            float ori = pi - SP[k];
            if (fabsf(ori) < TH) {
                float dd = di - SD[k];
                sq = fmaf(dd, dd, sq);
                cnt++;
            }
        }
    } else {
        for (int k = lo + js; k < hi; k += JSPLIT) {
            float ori = pi - g_spsi[wlo + k];
            if (fabsf(ori) < TH) {
                float dd = di - g_sdd[wlo + k];
                sq = fmaf(dd, dd, sq);
                cnt++;
            }
        }
    }

    float s = warp_sum_f(sq);
    int c = cnt;
#pragma unroll
    for (int o = 16; o > 0; o >>= 1) c += __shfl_down_sync(0xffffffffu, c, o);
    if ((tid & 31) == 0) { swf[tid >> 5] = s; swi[tid >> 5] = c; }
    __syncthreads();
    if (tid < 32) {
        float v = (tid < NT / 32) ? swf[tid] : 0.0f;
        int ci = (tid < NT / 32) ? swi[tid] : 0;
        v = warp_sum_f(v);
#pragma unroll
        for (int o = 16; o > 0; o >>= 1) ci += __shfl_down_sync(0xffffffffu, ci, o);
        if (tid == 0) { g_psq[blockIdx.x] = v; g_pcnt[blockIdx.x] = ci; }
    }
}

// ---------------------------------------------------------------------------
// Kernel 4: final assembly.
//   S_all   = 2N*sum(d^2) - 2*(sum d)^2          (closed form, exact math)
//   S_valid = S_all - S_invalid
//   n_valid = N^2 - C_invalid  (C_invalid includes diagonal; diag sq = 0)
// ---------------------------------------------------------------------------
__global__ void final_kernel(const int* __restrict__ flag,
                             float* __restrict__ out) {
    int t = threadIdx.x;
    double sq = 0.0; long long cnt = 0;
    if (t < PAIR_BLOCKS) { sq = (double)g_psq[t]; cnt = (long long)g_pcnt[t]; }
    double bce = 0.0, sd = 0.0, sd2 = 0.0;
    if (t < NBLK) { bce = (double)g_bce[t]; sd = (double)g_sd[t]; sd2 = (double)g_sd2[t]; }

#pragma unroll
    for (int o = 16; o > 0; o >>= 1) {
        sq  += __shfl_down_sync(0xffffffffu, sq, o);
        cnt += __shfl_down_sync(0xffffffffu, cnt, o);
        bce += __shfl_down_sync(0xffffffffu, bce, o);
        sd  += __shfl_down_sync(0xffffffffu, sd, o);
        sd2 += __shfl_down_sync(0xffffffffu, sd2, o);
    }
    __shared__ double    s_sq[NT / 32], s_b[NT / 32], s_sd[NT / 32], s_sd2[NT / 32];
    __shared__ long long s_c[NT / 32];
    if ((t & 31) == 0) {
        s_sq[t >> 5] = sq; s_c[t >> 5] = cnt;
        s_b[t >> 5] = bce; s_sd[t >> 5] = sd; s_sd2[t >> 5] = sd2;
    }
    __syncthreads();
    if (t == 0) {
        double SQ = 0, B = 0, SD = 0, SD2 = 0; long long C = 0;
        for (int w = 0; w < NT / 32; w++) {
            SQ += s_sq[w]; C += s_c[w]; B += s_b[w]; SD += s_sd[w]; SD2 += s_sd2[w];
        }
        double Sall = 2.0 * (double)N_ELEMS * SD2 - 2.0 * SD * SD;
        long long nvalid = (long long)N_ELEMS * (long long)N_ELEMS - C;
        float loss = (float)(B / (double)N_ELEMS);
        float res = loss;
        if (*flag == 0 && nvalid > 0) {
            double mse = (Sall - SQ) / (double)nvalid;
            res = loss + 10.0f * (float)mse;
        }
        out[0] = res;
    }
}

extern "C" void kernel_launch(void* const* d_in, const int* in_sizes, int n_in,
                              void* d_out, int out_size) {
    const float* pred = (const float*)d_in[0];
    const float* psi  = (const float*)d_in[1];
    const int*   flag = (const int*)d_in[2];
    float* out = (float*)d_out;

    prep_kernel<<<NBLK, NT>>>(pred, psi);
    scatter_kernel<<<NBLK, NT>>>(psi);
    pair_kernel<<<PAIR_BLOCKS, NT>>>();
    final_kernel<<<1, NT>>>(flag, out);
}